// round 1
// baseline (speedup 1.0000x reference)
#include <cuda_runtime.h>

// ---------------- problem constants ----------------
constexpr int B  = 2;
constexpr int C  = 16;
constexpr int H  = 384;
constexpr int W  = 1280;
constexpr int Ht = 96;
constexpr int Wt = 320;
constexpr int HW   = H * W;        // 491520
constexpr int FULL = B * H * W;    // 983040
constexpr int TIL  = Ht * Wt;      // 30720
constexpr int NT   = B * TIL;      // 61440
constexpr int Hp = 48, Wp = 160;   // prev hypothesis resolution

// ---------------- scratch (device globals; no allocation) ----------------
__device__ float g_upprev[B * 16 * TIL];
__device__ float g_sumabs[FULL];
__device__ float g_cv[6][FULL];      // [plane*3 + (k+1)][b*H*W + y*W + x]
__device__ float g_hA[B * 32 * TIL];
__device__ float g_hB[B * 32 * TIL];
__device__ float g_hC[B * 32 * TIL];
__device__ float g_u[B * 34 * TIL];

// ---------------- kernel 1: upsample_hyp(prev, scale=2, size=2) ----------------
__global__ void k_upsample(const float* __restrict__ prev) {
    int idx = blockIdx.x * blockDim.x + threadIdx.x;
    if (idx >= B * 16 * TIL) return;
    int x = idx % Wt;
    int y = (idx / Wt) % Ht;
    int c = (idx / TIL) % 16;
    int b = idx / (16 * TIL);
    int xh = x >> 1, yh = y >> 1;
    const float* p = prev + (size_t)b * 16 * Hp * Wp;
    int off = yh * Wp + xh;
    float v;
    if (c == 0) {
        float cx = (x & 1) ? 0.5f : -0.5f;
        float cy = (y & 1) ? 0.5f : -0.5f;
        v = 2.0f * (p[off] + cx * p[Hp * Wp + off] + cy * p[2 * Hp * Wp + off]);
    } else {
        v = p[c * Hp * Wp + off];
    }
    g_upprev[idx] = v;
}

// ---------------- kernel 2: fused fea + 6 cost volumes ----------------
// For each full-res pixel: sum|fea_l| and, for plane in {cur, up_prev} and
// k in {-1,0,1}:  cv = sum_c |fea_l - warp(fea_r, local_d)|
__global__ __launch_bounds__(128) void k_warpcv(const float* __restrict__ fea_l,
                                                const float* __restrict__ fea_r,
                                                const float* __restrict__ cur) {
    int idx = blockIdx.x * blockDim.x + threadIdx.x;
    if (idx >= FULL) return;
    int x = idx % W;
    int y = (idx / W) % H;
    int b = idx / (H * W);
    int ht = y >> 2, wt = x >> 2;
    float cx = (float)(x & 3) - 1.5f;   // linspace(-1.5,1.5,4)[x%4]
    float cy = (float)(y & 3) - 1.5f;

    int toff = b * 16 * TIL + ht * Wt + wt;
    float bc = cur[toff] + cx * cur[toff + TIL] + cy * cur[toff + 2 * TIL];
    float bp = g_upprev[toff] + cx * g_upprev[toff + TIL] + cy * g_upprev[toff + 2 * TIL];

    float w0a[6], w1a[6];
    int   xa[6], xb[6];
#pragma unroll
    for (int j = 0; j < 6; j++) {
        float ld = ((j < 3) ? bc : bp) + (float)(j % 3 - 1);
        float ix = (float)x - ld;
        float x0f = floorf(ix);
        float wx = ix - x0f;
        int x0 = (int)x0f;
        int x1 = x0 + 1;
        float o0 = (x0 >= 0 && x0 < W) ? 1.f : 0.f;
        float o1 = (x1 >= 0 && x1 < W) ? 1.f : 0.f;
        w0a[j] = (1.f - wx) * o0;
        w1a[j] = wx * o1;
        xa[j] = min(max(x0, 0), W - 1);
        xb[j] = min(max(x1, 0), W - 1);
    }

    float acc[6] = {0.f, 0.f, 0.f, 0.f, 0.f, 0.f};
    float sa = 0.f;
    const float* fl = fea_l + (size_t)b * C * HW + y * W + x;
    const float* fr = fea_r + (size_t)b * C * HW + y * W;
#pragma unroll 4
    for (int c = 0; c < C; c++) {
        float l = fl[c * HW];
        sa += fabsf(l);
        const float* r = fr + c * HW;
#pragma unroll
        for (int j = 0; j < 6; j++) {
            float v = w0a[j] * __ldg(r + xa[j]) + w1a[j] * __ldg(r + xb[j]);
            acc[j] += fabsf(l - v);
        }
    }
    g_sumabs[idx] = sa;
#pragma unroll
    for (int j = 0; j < 6; j++) g_cv[j][idx] = acc[j];
}

// ---------------- kernel 3: fused 1x1 convs (dec x2 + w0) ----------------
// Reads fea / cv in unshuffled form directly from full-res buffers.
__global__ __launch_bounds__(128) void k_fused1x1(const float* __restrict__ cur,
                                                  const float* __restrict__ w_dec,
                                                  const float* __restrict__ b_dec,
                                                  const float* __restrict__ w0,
                                                  const float* __restrict__ b0) {
    __shared__ float s_wd[64 * 16];  // [c][o] (o contiguous)
    __shared__ float s_w0[64 * 32];  // [c][o]
    __shared__ float s_bd[16], s_b0[32];
    for (int t = threadIdx.x; t < 64 * 16; t += blockDim.x) {
        int c = t >> 4, o = t & 15;
        s_wd[t] = w_dec[o * 64 + c];
    }
    for (int t = threadIdx.x; t < 64 * 32; t += blockDim.x) {
        int c = t >> 5, o = t & 31;
        s_w0[t] = w0[o * 64 + c];
    }
    if (threadIdx.x < 16) s_bd[threadIdx.x] = b_dec[threadIdx.x];
    if (threadIdx.x < 32) s_b0[threadIdx.x] = b0[threadIdx.x];
    __syncthreads();

    int idx = blockIdx.x * blockDim.x + threadIdx.x;
    if (idx >= NT) return;
    int wt = idx % Wt;
    int ht = (idx / Wt) % Ht;
    int b = idx / TIL;

    float ac[16], ap[16];
#pragma unroll
    for (int o = 0; o < 16; o++) { ac[o] = s_bd[o]; ap[o] = s_bd[o]; }

#pragma unroll
    for (int c = 0; c < 64; c++) {
        int ry = (c >> 2) & 3, rx = c & 3;
        int fidx = (b * H + 4 * ht + ry) * W + 4 * wt + rx;
        float vc, vp;
        if (c < 16) {
            float s = g_sumabs[fidx];
            vc = s; vp = s;
        } else {
            int k = (c - 16) >> 4;
            vc = g_cv[k][fidx];
            vp = g_cv[3 + k][fidx];
        }
        const float4* wp = (const float4*)&s_wd[c * 16];
#pragma unroll
        for (int q = 0; q < 4; q++) {
            float4 w4 = wp[q];
            ac[4 * q + 0] += w4.x * vc; ac[4 * q + 1] += w4.y * vc;
            ac[4 * q + 2] += w4.z * vc; ac[4 * q + 3] += w4.w * vc;
            ap[4 * q + 0] += w4.x * vp; ap[4 * q + 1] += w4.y * vp;
            ap[4 * q + 2] += w4.z * vp; ap[4 * q + 3] += w4.w * vp;
        }
    }
#pragma unroll
    for (int o = 0; o < 16; o++) {
        ac[o] = ac[o] >= 0.f ? ac[o] : 0.2f * ac[o];
        ap[o] = ap[o] >= 0.f ? ap[o] : 0.2f * ap[o];
    }

    float ah[32];
#pragma unroll
    for (int o = 0; o < 32; o++) ah[o] = s_b0[o];
    int tb = b * 16 * TIL + ht * Wt + wt;
#pragma unroll
    for (int c = 0; c < 64; c++) {
        float v;
        if (c < 16)       v = cur[tb + c * TIL];
        else if (c < 32)  v = ac[c - 16];
        else if (c < 48)  v = g_upprev[tb + (c - 32) * TIL];
        else              v = ap[c - 48];
        const float4* wp = (const float4*)&s_w0[c * 32];
#pragma unroll
        for (int q = 0; q < 8; q++) {
            float4 w4 = wp[q];
            ah[4 * q + 0] += w4.x * v; ah[4 * q + 1] += w4.y * v;
            ah[4 * q + 2] += w4.z * v; ah[4 * q + 3] += w4.w * v;
        }
    }
    int ob = b * 32 * TIL + ht * Wt + wt;
#pragma unroll
    for (int o = 0; o < 32; o++) {
        float v = ah[o];
        v = v >= 0.f ? v : 0.2f * v;
        g_hA[ob + o * TIL] = v;
    }
}

// ---------------- kernel 4: 3x3 conv, pad=1, 32 in channels ----------------
template <int OC, bool RES, bool LEAKY>
__global__ __launch_bounds__(256) void k_conv3(const float* __restrict__ in,
                                               const float* __restrict__ res,
                                               const float* __restrict__ w,
                                               const float* __restrict__ bias,
                                               float* __restrict__ out) {
    constexpr int OCP = (OC + 3) & ~3;
    extern __shared__ float sm[];
    float* s_in = sm;                     // [32][10][34]
    float* s_w  = sm + 32 * 10 * 34;      // [ci][tap][OCP]

    int tx = threadIdx.x, ty = threadIdx.y;
    int tid = ty * 32 + tx;
    int x0 = blockIdx.x * 32, y0 = blockIdx.y * 8, b = blockIdx.z;

    for (int t = tid; t < 32 * 9 * OCP; t += 256) {
        int o = t % OCP;
        int ct = t / OCP;
        int ci = ct / 9, tap = ct % 9;
        s_w[t] = (o < OC) ? w[(o * 32 + ci) * 9 + tap] : 0.f;
    }
    for (int t = tid; t < 32 * 10 * 34; t += 256) {
        int ci = t / 340;
        int rm = t % 340;
        int r = rm / 34, c2 = rm % 34;
        int gy = y0 + r - 1, gx = x0 + c2 - 1;
        float v = 0.f;
        if (gy >= 0 && gy < Ht && gx >= 0 && gx < Wt)
            v = in[((b * 32 + ci) * Ht + gy) * Wt + gx];
        s_in[t] = v;
    }
    __syncthreads();

    float acc[OCP];
#pragma unroll
    for (int o = 0; o < OCP; o++) acc[o] = (o < OC) ? __ldg(bias + o) : 0.f;

#pragma unroll 4
    for (int ci = 0; ci < 32; ci++) {
        const float* si = s_in + ci * 340 + ty * 34 + tx;
#pragma unroll
        for (int t = 0; t < 9; t++) {
            float v = si[(t / 3) * 34 + (t % 3)];
            const float4* wp = (const float4*)(s_w + (ci * 9 + t) * OCP);
#pragma unroll
            for (int q = 0; q < OCP / 4; q++) {
                float4 w4 = wp[q];
                acc[4 * q + 0] += w4.x * v;
                acc[4 * q + 1] += w4.y * v;
                acc[4 * q + 2] += w4.z * v;
                acc[4 * q + 3] += w4.w * v;
            }
        }
    }

    int y = y0 + ty, x = x0 + tx;
#pragma unroll
    for (int o = 0; o < OC; o++) {
        float v = acc[o];
        if (RES) v += res[((b * 32 + o) * Ht + y) * Wt + x];
        if (LEAKY) v = v >= 0.f ? v : 0.2f * v;
        out[((b * OC + o) * Ht + y) * Wt + x] = v;
    }
}

// ---------------- kernel 5: mask/select epilogue + output packing ----------------
__global__ void k_final(const float* __restrict__ cur, float* __restrict__ out) {
    int idx = blockIdx.x * blockDim.x + threadIdx.x;
    if (idx >= NT) return;
    int wt = idx % Wt;
    int ht = (idx / Wt) % Ht;
    int b = idx / TIL;
    int p = ht * Wt + wt;
    const float* u = g_u + b * 34 * TIL + p;
    float c0 = u[0];
    float c1 = u[TIL];
    bool pick_cur = (c1 > c0);   // argmax with ties -> index 0

    float* o1 = out + b * 16 * TIL + p;
    float* o2 = out + B * 16 * TIL + b * 17 * TIL + p;
    float* o3 = out + B * 16 * TIL + B * 17 * TIL + b * 17 * TIL + p;
#pragma unroll
    for (int c = 0; c < 16; c++) {
        float uc = cur[b * 16 * TIL + c * TIL + p] + u[(18 + c) * TIL];
        float up = g_upprev[b * 16 * TIL + c * TIL + p] + u[(2 + c) * TIL];
        if (c == 0) { uc = fmaxf(uc, 0.f); up = fmaxf(up, 0.f); }
        o1[c * TIL] = pick_cur ? uc : up;
        o2[c * TIL] = uc;
        o3[c * TIL] = up;
    }
    o2[16 * TIL] = c1;
    o3[16 * TIL] = c0;
}

// ---------------- launch ----------------
extern "C" void kernel_launch(void* const* d_in, const int* in_sizes, int n_in,
                              void* d_out, int out_size) {
    const float* fea_l  = (const float*)d_in[0];
    const float* fea_r  = (const float*)d_in[1];
    const float* cur    = (const float*)d_in[2];
    const float* prev   = (const float*)d_in[3];
    const float* w_dec  = (const float*)d_in[4];
    const float* b_dec  = (const float*)d_in[5];
    const float* w0     = (const float*)d_in[6];
    const float* b0     = (const float*)d_in[7];
    const float* w_r0c1 = (const float*)d_in[8];
    const float* b_r0c1 = (const float*)d_in[9];
    const float* w_r0c2 = (const float*)d_in[10];
    const float* b_r0c2 = (const float*)d_in[11];
    const float* w_r1c1 = (const float*)d_in[12];
    const float* b_r1c1 = (const float*)d_in[13];
    const float* w_r1c2 = (const float*)d_in[14];
    const float* b_r1c2 = (const float*)d_in[15];
    const float* w_last = (const float*)d_in[16];
    const float* b_last = (const float*)d_in[17];
    float* out = (float*)d_out;

    void *pA, *pB, *pC, *pU;
    cudaGetSymbolAddress(&pA, g_hA);
    cudaGetSymbolAddress(&pB, g_hB);
    cudaGetSymbolAddress(&pC, g_hC);
    cudaGetSymbolAddress(&pU, g_u);
    float* hA = (float*)pA;
    float* hB = (float*)pB;
    float* hC = (float*)pC;
    float* uB = (float*)pU;

    constexpr int SM32 = (32 * 10 * 34 + 32 * 9 * 32) * 4;   // 80384 B
    constexpr int SM34 = (32 * 10 * 34 + 32 * 9 * 36) * 4;   // 84992 B
    cudaFuncSetAttribute(k_conv3<32, false, true>,
                         cudaFuncAttributeMaxDynamicSharedMemorySize, SM32);
    cudaFuncSetAttribute(k_conv3<32, true, true>,
                         cudaFuncAttributeMaxDynamicSharedMemorySize, SM32);
    cudaFuncSetAttribute(k_conv3<34, false, false>,
                         cudaFuncAttributeMaxDynamicSharedMemorySize, SM34);

    // 1. up_prev
    k_upsample<<<(B * 16 * TIL + 255) / 256, 256>>>(prev);
    // 2. fea + 6 cost volumes (full res)
    k_warpcv<<<(FULL + 127) / 128, 128>>>(fea_l, fea_r, cur);
    // 3. dec convs + w0 -> hA
    k_fused1x1<<<(NT + 127) / 128, 128>>>(cur, w_dec, b_dec, w0, b0);

    dim3 cb(32, 8);
    dim3 cg(Wt / 32, Ht / 8, B);
    // 4. residual trunk
    k_conv3<32, false, true><<<cg, cb, SM32>>>(hA, nullptr, w_r0c1, b_r0c1, hB);
    k_conv3<32, true,  true><<<cg, cb, SM32>>>(hB, hA, w_r0c2, b_r0c2, hC);
    k_conv3<32, false, true><<<cg, cb, SM32>>>(hC, nullptr, w_r1c1, b_r1c1, hB);
    k_conv3<32, true,  true><<<cg, cb, SM32>>>(hB, hC, w_r1c2, b_r1c2, hA);
    k_conv3<34, false, false><<<cg, cb, SM34>>>(hA, nullptr, w_last, b_last, uB);
    // 5. epilogue
    k_final<<<(NT + 255) / 256, 256>>>(cur, out);
}

// round 2
// speedup vs baseline: 1.1475x; 1.1475x over previous
#include <cuda_runtime.h>
#include <cstdint>

// ---------------- problem constants ----------------
constexpr int B  = 2;
constexpr int C  = 16;
constexpr int H  = 384;
constexpr int W  = 1280;
constexpr int Ht = 96;
constexpr int Wt = 320;
constexpr int HW   = H * W;        // 491520
constexpr int FULL = B * H * W;    // 983040
constexpr int TIL  = Ht * Wt;      // 30720
constexpr int NT   = B * TIL;      // 61440
constexpr int Hp = 48, Wp = 160;   // prev hypothesis resolution

// ---------------- scratch (device globals; no allocation) ----------------
__device__ float g_upprev[B * 16 * TIL];
__device__ float g_sumabs[FULL];
__device__ float g_cv[6][FULL];      // [plane*3 + (k+1)][b*H*W + y*W + x]
__device__ float g_hA[B * 32 * TIL];
__device__ float g_hB[B * 32 * TIL];
__device__ float g_hC[B * 32 * TIL];
__device__ float g_u[B * 34 * TIL];

// ---------------- f32x2 packed helpers ----------------
__device__ __forceinline__ void ffma2(uint64_t& d, uint64_t a, uint64_t b) {
    asm("fma.rn.f32x2 %0, %1, %2, %0;" : "+l"(d) : "l"(a), "l"(b));
}
__device__ __forceinline__ uint64_t pack2(float lo, float hi) {
    uint64_t r;
    asm("mov.b64 %0, {%1, %2};" : "=l"(r) : "f"(lo), "f"(hi));
    return r;
}
__device__ __forceinline__ uint64_t bcast2(float v) {
    uint64_t r;
    asm("mov.b64 %0, {%1, %1};" : "=l"(r) : "f"(v));
    return r;
}
__device__ __forceinline__ void unpack2(uint64_t a, float& lo, float& hi) {
    asm("mov.b64 {%0, %1}, %2;" : "=f"(lo), "=f"(hi) : "l"(a));
}

// ---------------- kernel 1: upsample_hyp(prev, scale=2, size=2) ----------------
__global__ void k_upsample(const float* __restrict__ prev) {
    int idx = blockIdx.x * blockDim.x + threadIdx.x;
    if (idx >= B * 16 * TIL) return;
    int x = idx % Wt;
    int y = (idx / Wt) % Ht;
    int c = (idx / TIL) % 16;
    int b = idx / (16 * TIL);
    int xh = x >> 1, yh = y >> 1;
    const float* p = prev + (size_t)b * 16 * Hp * Wp;
    int off = yh * Wp + xh;
    float v;
    if (c == 0) {
        float cx = (x & 1) ? 0.5f : -0.5f;
        float cy = (y & 1) ? 0.5f : -0.5f;
        v = 2.0f * (p[off] + cx * p[Hp * Wp + off] + cy * p[2 * Hp * Wp + off]);
    } else {
        v = p[c * Hp * Wp + off];
    }
    g_upprev[idx] = v;
}

// ---------------- kernel 2: fused fea + 6 cost volumes ----------------
__global__ __launch_bounds__(128) void k_warpcv(const float* __restrict__ fea_l,
                                                const float* __restrict__ fea_r,
                                                const float* __restrict__ cur) {
    int idx = blockIdx.x * blockDim.x + threadIdx.x;
    if (idx >= FULL) return;
    int x = idx % W;
    int y = (idx / W) % H;
    int b = idx / (H * W);
    int ht = y >> 2, wt = x >> 2;
    float cx = (float)(x & 3) - 1.5f;
    float cy = (float)(y & 3) - 1.5f;

    int toff = b * 16 * TIL + ht * Wt + wt;
    float bc = cur[toff] + cx * cur[toff + TIL] + cy * cur[toff + 2 * TIL];
    float bp = g_upprev[toff] + cx * g_upprev[toff + TIL] + cy * g_upprev[toff + 2 * TIL];

    float w0a[6], w1a[6];
    int   xa[6], xb[6];
#pragma unroll
    for (int j = 0; j < 6; j++) {
        float ld = ((j < 3) ? bc : bp) + (float)(j % 3 - 1);
        float ix = (float)x - ld;
        float x0f = floorf(ix);
        float wx = ix - x0f;
        int x0 = (int)x0f;
        int x1 = x0 + 1;
        float o0 = (x0 >= 0 && x0 < W) ? 1.f : 0.f;
        float o1 = (x1 >= 0 && x1 < W) ? 1.f : 0.f;
        w0a[j] = (1.f - wx) * o0;
        w1a[j] = wx * o1;
        xa[j] = min(max(x0, 0), W - 1);
        xb[j] = min(max(x1, 0), W - 1);
    }

    float acc[6] = {0.f, 0.f, 0.f, 0.f, 0.f, 0.f};
    float sa = 0.f;
    const float* fl = fea_l + (size_t)b * C * HW + y * W + x;
    const float* fr = fea_r + (size_t)b * C * HW + y * W;
#pragma unroll 4
    for (int c = 0; c < C; c++) {
        float l = fl[c * HW];
        sa += fabsf(l);
        const float* r = fr + c * HW;
#pragma unroll
        for (int j = 0; j < 6; j++) {
            float v = w0a[j] * __ldg(r + xa[j]) + w1a[j] * __ldg(r + xb[j]);
            acc[j] += fabsf(l - v);
        }
    }
    g_sumabs[idx] = sa;
#pragma unroll
    for (int j = 0; j < 6; j++) g_cv[j][idx] = acc[j];
}

// ---------------- kernel 3: fused 1x1 convs (dec x2 + w0) ----------------
__global__ __launch_bounds__(128) void k_fused1x1(const float* __restrict__ cur,
                                                  const float* __restrict__ w_dec,
                                                  const float* __restrict__ b_dec,
                                                  const float* __restrict__ w0,
                                                  const float* __restrict__ b0) {
    __shared__ float s_wd[64 * 16];  // [c][o]
    __shared__ float s_w0[64 * 32];  // [c][o]
    __shared__ float s_bd[16], s_b0[32];
    for (int t = threadIdx.x; t < 64 * 16; t += blockDim.x) {
        int c = t >> 4, o = t & 15;
        s_wd[t] = w_dec[o * 64 + c];
    }
    for (int t = threadIdx.x; t < 64 * 32; t += blockDim.x) {
        int c = t >> 5, o = t & 31;
        s_w0[t] = w0[o * 64 + c];
    }
    if (threadIdx.x < 16) s_bd[threadIdx.x] = b_dec[threadIdx.x];
    if (threadIdx.x < 32) s_b0[threadIdx.x] = b0[threadIdx.x];
    __syncthreads();

    int idx = blockIdx.x * blockDim.x + threadIdx.x;
    if (idx >= NT) return;
    int wt = idx % Wt;
    int ht = (idx / Wt) % Ht;
    int b = idx / TIL;

    float ac[16], ap[16];
#pragma unroll
    for (int o = 0; o < 16; o++) { ac[o] = s_bd[o]; ap[o] = s_bd[o]; }

#pragma unroll
    for (int c = 0; c < 64; c++) {
        int ry = (c >> 2) & 3, rx = c & 3;
        int fidx = (b * H + 4 * ht + ry) * W + 4 * wt + rx;
        float vc, vp;
        if (c < 16) {
            float s = g_sumabs[fidx];
            vc = s; vp = s;
        } else {
            int k = (c - 16) >> 4;
            vc = g_cv[k][fidx];
            vp = g_cv[3 + k][fidx];
        }
        const float4* wp = (const float4*)&s_wd[c * 16];
#pragma unroll
        for (int q = 0; q < 4; q++) {
            float4 w4 = wp[q];
            ac[4 * q + 0] += w4.x * vc; ac[4 * q + 1] += w4.y * vc;
            ac[4 * q + 2] += w4.z * vc; ac[4 * q + 3] += w4.w * vc;
            ap[4 * q + 0] += w4.x * vp; ap[4 * q + 1] += w4.y * vp;
            ap[4 * q + 2] += w4.z * vp; ap[4 * q + 3] += w4.w * vp;
        }
    }
#pragma unroll
    for (int o = 0; o < 16; o++) {
        ac[o] = ac[o] >= 0.f ? ac[o] : 0.2f * ac[o];
        ap[o] = ap[o] >= 0.f ? ap[o] : 0.2f * ap[o];
    }

    float ah[32];
#pragma unroll
    for (int o = 0; o < 32; o++) ah[o] = s_b0[o];
    int tb = b * 16 * TIL + ht * Wt + wt;
#pragma unroll
    for (int c = 0; c < 64; c++) {
        float v;
        if (c < 16)       v = cur[tb + c * TIL];
        else if (c < 32)  v = ac[c - 16];
        else if (c < 48)  v = g_upprev[tb + (c - 32) * TIL];
        else              v = ap[c - 48];
        const float4* wp = (const float4*)&s_w0[c * 32];
#pragma unroll
        for (int q = 0; q < 8; q++) {
            float4 w4 = wp[q];
            ah[4 * q + 0] += w4.x * v; ah[4 * q + 1] += w4.y * v;
            ah[4 * q + 2] += w4.z * v; ah[4 * q + 3] += w4.w * v;
        }
    }
    int ob = b * 32 * TIL + ht * Wt + wt;
#pragma unroll
    for (int o = 0; o < 32; o++) {
        float v = ah[o];
        v = v >= 0.f ? v : 0.2f * v;
        g_hA[ob + o * TIL] = v;
    }
}

// ---------------- kernel 4: 3x3 conv, pad=1, 32 in channels, f32x2 packed ----
// Block (32,4) = 128 threads. Tile 32 wide x 8 tall; each thread computes
// 2 vertically-adjacent pixels (rows ty*2, ty*2+1), accumulating output
// channel PAIRS in 64-bit registers via fma.rn.f32x2 (SASS FFMA2).
template <int OC, bool RES, bool LEAKY>
__global__ __launch_bounds__(128) void k_conv3(const float* __restrict__ in,
                                               const float* __restrict__ res,
                                               const float* __restrict__ w,
                                               const float* __restrict__ bias,
                                               float* __restrict__ out) {
    constexpr int OCP = (OC + 3) & ~3;      // 32 or 36
    constexpr int NP  = OCP / 2;            // packed pairs: 16 or 18
    constexpr int NQ  = OCP / 4;            // ulonglong2 chunks: 8 or 9
    extern __shared__ float sm[];
    float* s_in = sm;                       // [32][10][34]
    float* s_w  = sm + 32 * 10 * 34;        // [ci][tap][OCP]

    int tx = threadIdx.x, ty = threadIdx.y;
    int tid = ty * 32 + tx;
    int x0 = blockIdx.x * 32, y0 = blockIdx.y * 8, b = blockIdx.z;

    for (int t = tid; t < 32 * 9 * OCP; t += 128) {
        int o = t % OCP;
        int ct = t / OCP;
        int ci = ct / 9, tap = ct % 9;
        s_w[t] = (o < OC) ? w[(o * 32 + ci) * 9 + tap] : 0.f;
    }
    for (int t = tid; t < 32 * 10 * 34; t += 128) {
        int ci = t / 340;
        int rm = t % 340;
        int r = rm / 34, c2 = rm % 34;
        int gy = y0 + r - 1, gx = x0 + c2 - 1;
        float v = 0.f;
        if (gy >= 0 && gy < Ht && gx >= 0 && gx < Wt)
            v = in[((b * 32 + ci) * Ht + gy) * Wt + gx];
        s_in[t] = v;
    }
    __syncthreads();

    uint64_t acc[2][NP];
#pragma unroll
    for (int q = 0; q < NP; q++) {
        float blo = (2 * q     < OC) ? __ldg(bias + 2 * q)     : 0.f;
        float bhi = (2 * q + 1 < OC) ? __ldg(bias + 2 * q + 1) : 0.f;
        uint64_t bp = pack2(blo, bhi);
        acc[0][q] = bp;
        acc[1][q] = bp;
    }

    int yloc = ty * 2;   // output rows yloc, yloc+1; s_in rows yloc..yloc+3
#pragma unroll 2
    for (int ci = 0; ci < 32; ci++) {
        const float* si = s_in + ci * 340 + yloc * 34 + tx;
        // 4x3 input window, broadcast-packed
        uint64_t iv[4][3];
#pragma unroll
        for (int rr = 0; rr < 4; rr++)
#pragma unroll
            for (int cc = 0; cc < 3; cc++)
                iv[rr][cc] = bcast2(si[rr * 34 + cc]);

#pragma unroll
        for (int t = 0; t < 9; t++) {
            int dr = t / 3, dc = t % 3;
            const ulonglong2* wp = (const ulonglong2*)(s_w + (ci * 9 + t) * OCP);
#pragma unroll
            for (int q = 0; q < NQ; q++) {
                ulonglong2 w2 = wp[q];
                ffma2(acc[0][2 * q],     iv[dr][dc],     w2.x);
                ffma2(acc[0][2 * q + 1], iv[dr][dc],     w2.y);
                ffma2(acc[1][2 * q],     iv[dr + 1][dc], w2.x);
                ffma2(acc[1][2 * q + 1], iv[dr + 1][dc], w2.y);
            }
        }
    }

    int x = x0 + tx;
#pragma unroll
    for (int r = 0; r < 2; r++) {
        int y = y0 + yloc + r;
#pragma unroll
        for (int q = 0; q < NP; q++) {
            float v0, v1;
            unpack2(acc[r][q], v0, v1);
            int o0 = 2 * q, o1 = 2 * q + 1;
            if (o0 < OC) {
                if (RES) v0 += res[((b * 32 + o0) * Ht + y) * Wt + x];
                if (LEAKY) v0 = v0 >= 0.f ? v0 : 0.2f * v0;
                out[((b * OC + o0) * Ht + y) * Wt + x] = v0;
            }
            if (o1 < OC) {
                if (RES) v1 += res[((b * 32 + o1) * Ht + y) * Wt + x];
                if (LEAKY) v1 = v1 >= 0.f ? v1 : 0.2f * v1;
                out[((b * OC + o1) * Ht + y) * Wt + x] = v1;
            }
        }
    }
}

// ---------------- kernel 5: mask/select epilogue + output packing ----------------
__global__ void k_final(const float* __restrict__ cur, float* __restrict__ out) {
    int idx = blockIdx.x * blockDim.x + threadIdx.x;
    if (idx >= NT) return;
    int wt = idx % Wt;
    int ht = (idx / Wt) % Ht;
    int b = idx / TIL;
    int p = ht * Wt + wt;
    const float* u = g_u + b * 34 * TIL + p;
    float c0 = u[0];
    float c1 = u[TIL];
    bool pick_cur = (c1 > c0);

    float* o1 = out + b * 16 * TIL + p;
    float* o2 = out + B * 16 * TIL + b * 17 * TIL + p;
    float* o3 = out + B * 16 * TIL + B * 17 * TIL + b * 17 * TIL + p;
#pragma unroll
    for (int c = 0; c < 16; c++) {
        float uc = cur[b * 16 * TIL + c * TIL + p] + u[(18 + c) * TIL];
        float up = g_upprev[b * 16 * TIL + c * TIL + p] + u[(2 + c) * TIL];
        if (c == 0) { uc = fmaxf(uc, 0.f); up = fmaxf(up, 0.f); }
        o1[c * TIL] = pick_cur ? uc : up;
        o2[c * TIL] = uc;
        o3[c * TIL] = up;
    }
    o2[16 * TIL] = c1;
    o3[16 * TIL] = c0;
}

// ---------------- launch ----------------
extern "C" void kernel_launch(void* const* d_in, const int* in_sizes, int n_in,
                              void* d_out, int out_size) {
    const float* fea_l  = (const float*)d_in[0];
    const float* fea_r  = (const float*)d_in[1];
    const float* cur    = (const float*)d_in[2];
    const float* prev   = (const float*)d_in[3];
    const float* w_dec  = (const float*)d_in[4];
    const float* b_dec  = (const float*)d_in[5];
    const float* w0     = (const float*)d_in[6];
    const float* b0     = (const float*)d_in[7];
    const float* w_r0c1 = (const float*)d_in[8];
    const float* b_r0c1 = (const float*)d_in[9];
    const float* w_r0c2 = (const float*)d_in[10];
    const float* b_r0c2 = (const float*)d_in[11];
    const float* w_r1c1 = (const float*)d_in[12];
    const float* b_r1c1 = (const float*)d_in[13];
    const float* w_r1c2 = (const float*)d_in[14];
    const float* b_r1c2 = (const float*)d_in[15];
    const float* w_last = (const float*)d_in[16];
    const float* b_last = (const float*)d_in[17];
    float* out = (float*)d_out;

    void *pA, *pB, *pC, *pU;
    cudaGetSymbolAddress(&pA, g_hA);
    cudaGetSymbolAddress(&pB, g_hB);
    cudaGetSymbolAddress(&pC, g_hC);
    cudaGetSymbolAddress(&pU, g_u);
    float* hA = (float*)pA;
    float* hB = (float*)pB;
    float* hC = (float*)pC;
    float* uB = (float*)pU;

    constexpr int SM32 = (32 * 10 * 34 + 32 * 9 * 32) * 4;   // 80384 B
    constexpr int SM34 = (32 * 10 * 34 + 32 * 9 * 36) * 4;   // 84992 B
    cudaFuncSetAttribute(k_conv3<32, false, true>,
                         cudaFuncAttributeMaxDynamicSharedMemorySize, SM32);
    cudaFuncSetAttribute(k_conv3<32, true, true>,
                         cudaFuncAttributeMaxDynamicSharedMemorySize, SM32);
    cudaFuncSetAttribute(k_conv3<34, false, false>,
                         cudaFuncAttributeMaxDynamicSharedMemorySize, SM34);

    k_upsample<<<(B * 16 * TIL + 255) / 256, 256>>>(prev);
    k_warpcv<<<(FULL + 127) / 128, 128>>>(fea_l, fea_r, cur);
    k_fused1x1<<<(NT + 127) / 128, 128>>>(cur, w_dec, b_dec, w0, b0);

    dim3 cb(32, 4);
    dim3 cg(Wt / 32, Ht / 8, B);
    k_conv3<32, false, true><<<cg, cb, SM32>>>(hA, nullptr, w_r0c1, b_r0c1, hB);
    k_conv3<32, true,  true><<<cg, cb, SM32>>>(hB, hA, w_r0c2, b_r0c2, hC);
    k_conv3<32, false, true><<<cg, cb, SM32>>>(hC, nullptr, w_r1c1, b_r1c1, hB);
    k_conv3<32, true,  true><<<cg, cb, SM32>>>(hB, hC, w_r1c2, b_r1c2, hA);
    k_conv3<34, false, false><<<cg, cb, SM34>>>(hA, nullptr, w_last, b_last, uB);
    k_final<<<(NT + 255) / 256, 256>>>(cur, out);
}

// round 3
// speedup vs baseline: 1.1539x; 1.0056x over previous
#include <cuda_runtime.h>
#include <cstdint>

// ---------------- problem constants ----------------
constexpr int B  = 2;
constexpr int C  = 16;
constexpr int H  = 384;
constexpr int W  = 1280;
constexpr int Ht = 96;
constexpr int Wt = 320;
constexpr int HW   = H * W;        // 491520
constexpr int FULL = B * H * W;    // 983040
constexpr int TIL  = Ht * Wt;      // 30720
constexpr int NT   = B * TIL;      // 61440
constexpr int Hp = 48, Wp = 160;   // prev hypothesis resolution

// ---------------- scratch (device globals; no allocation) ----------------
__device__ float g_upprev[B * 16 * TIL];
__device__ float g_sumabs[FULL];
__device__ float g_cv[6][FULL];
__device__ float g_hA[B * 32 * TIL];
__device__ float g_hB[B * 32 * TIL];
__device__ float g_hC[B * 32 * TIL];
__device__ float g_u[B * 34 * TIL];

// ---------------- f32x2 packed helpers ----------------
__device__ __forceinline__ void ffma2(uint64_t& d, uint64_t a, uint64_t b) {
    asm("fma.rn.f32x2 %0, %1, %2, %0;" : "+l"(d) : "l"(a), "l"(b));
}
__device__ __forceinline__ uint64_t pack2(float lo, float hi) {
    uint64_t r;
    asm("mov.b64 %0, {%1, %2};" : "=l"(r) : "f"(lo), "f"(hi));
    return r;
}
__device__ __forceinline__ uint64_t bcast2(float v) {
    uint64_t r;
    asm("mov.b64 %0, {%1, %1};" : "=l"(r) : "f"(v));
    return r;
}
__device__ __forceinline__ void unpack2(uint64_t a, float& lo, float& hi) {
    asm("mov.b64 {%0, %1}, %2;" : "=f"(lo), "=f"(hi) : "l"(a));
}

// ---------------- kernel 1: upsample_hyp(prev, scale=2, size=2) ----------------
__global__ void k_upsample(const float* __restrict__ prev) {
    int idx = blockIdx.x * blockDim.x + threadIdx.x;
    if (idx >= B * 16 * TIL) return;
    int x = idx % Wt;
    int y = (idx / Wt) % Ht;
    int c = (idx / TIL) % 16;
    int b = idx / (16 * TIL);
    int xh = x >> 1, yh = y >> 1;
    const float* p = prev + (size_t)b * 16 * Hp * Wp;
    int off = yh * Wp + xh;
    float v;
    if (c == 0) {
        float cx = (x & 1) ? 0.5f : -0.5f;
        float cy = (y & 1) ? 0.5f : -0.5f;
        v = 2.0f * (p[off] + cx * p[Hp * Wp + off] + cy * p[2 * Hp * Wp + off]);
    } else {
        v = p[c * Hp * Wp + off];
    }
    g_upprev[idx] = v;
}

// ---------------- kernel 2: fused fea + 6 cost volumes ----------------
__global__ __launch_bounds__(128) void k_warpcv(const float* __restrict__ fea_l,
                                                const float* __restrict__ fea_r,
                                                const float* __restrict__ cur) {
    int idx = blockIdx.x * blockDim.x + threadIdx.x;
    if (idx >= FULL) return;
    int x = idx % W;
    int y = (idx / W) % H;
    int b = idx / (H * W);
    int ht = y >> 2, wt = x >> 2;
    float cx = (float)(x & 3) - 1.5f;
    float cy = (float)(y & 3) - 1.5f;

    int toff = b * 16 * TIL + ht * Wt + wt;
    float bc = cur[toff] + cx * cur[toff + TIL] + cy * cur[toff + 2 * TIL];
    float bp = g_upprev[toff] + cx * g_upprev[toff + TIL] + cy * g_upprev[toff + 2 * TIL];

    float w0a[6], w1a[6];
    int   xa[6], xb[6];
#pragma unroll
    for (int j = 0; j < 6; j++) {
        float ld = ((j < 3) ? bc : bp) + (float)(j % 3 - 1);
        float ix = (float)x - ld;
        float x0f = floorf(ix);
        float wx = ix - x0f;
        int x0 = (int)x0f;
        int x1 = x0 + 1;
        float o0 = (x0 >= 0 && x0 < W) ? 1.f : 0.f;
        float o1 = (x1 >= 0 && x1 < W) ? 1.f : 0.f;
        w0a[j] = (1.f - wx) * o0;
        w1a[j] = wx * o1;
        xa[j] = min(max(x0, 0), W - 1);
        xb[j] = min(max(x1, 0), W - 1);
    }

    float acc[6] = {0.f, 0.f, 0.f, 0.f, 0.f, 0.f};
    float sa = 0.f;
    const float* fl = fea_l + (size_t)b * C * HW + y * W + x;
    const float* fr = fea_r + (size_t)b * C * HW + y * W;
#pragma unroll 4
    for (int c = 0; c < C; c++) {
        float l = fl[c * HW];
        sa += fabsf(l);
        const float* r = fr + c * HW;
#pragma unroll
        for (int j = 0; j < 6; j++) {
            float v = w0a[j] * __ldg(r + xa[j]) + w1a[j] * __ldg(r + xb[j]);
            acc[j] += fabsf(l - v);
        }
    }
    g_sumabs[idx] = sa;
#pragma unroll
    for (int j = 0; j < 6; j++) g_cv[j][idx] = acc[j];
}

// ---------------- kernel 3: fused 1x1 convs (dec x2 + w0) ----------------
__global__ __launch_bounds__(128) void k_fused1x1(const float* __restrict__ cur,
                                                  const float* __restrict__ w_dec,
                                                  const float* __restrict__ b_dec,
                                                  const float* __restrict__ w0,
                                                  const float* __restrict__ b0) {
    __shared__ float s_wd[64 * 16];
    __shared__ float s_w0[64 * 32];
    __shared__ float s_bd[16], s_b0[32];
    for (int t = threadIdx.x; t < 64 * 16; t += blockDim.x) {
        int c = t >> 4, o = t & 15;
        s_wd[t] = w_dec[o * 64 + c];
    }
    for (int t = threadIdx.x; t < 64 * 32; t += blockDim.x) {
        int c = t >> 5, o = t & 31;
        s_w0[t] = w0[o * 64 + c];
    }
    if (threadIdx.x < 16) s_bd[threadIdx.x] = b_dec[threadIdx.x];
    if (threadIdx.x < 32) s_b0[threadIdx.x] = b0[threadIdx.x];
    __syncthreads();

    int idx = blockIdx.x * blockDim.x + threadIdx.x;
    if (idx >= NT) return;
    int wt = idx % Wt;
    int ht = (idx / Wt) % Ht;
    int b = idx / TIL;

    float ac[16], ap[16];
#pragma unroll
    for (int o = 0; o < 16; o++) { ac[o] = s_bd[o]; ap[o] = s_bd[o]; }

#pragma unroll
    for (int c = 0; c < 64; c++) {
        int ry = (c >> 2) & 3, rx = c & 3;
        int fidx = (b * H + 4 * ht + ry) * W + 4 * wt + rx;
        float vc, vp;
        if (c < 16) {
            float s = g_sumabs[fidx];
            vc = s; vp = s;
        } else {
            int k = (c - 16) >> 4;
            vc = g_cv[k][fidx];
            vp = g_cv[3 + k][fidx];
        }
        const float4* wp = (const float4*)&s_wd[c * 16];
#pragma unroll
        for (int q = 0; q < 4; q++) {
            float4 w4 = wp[q];
            ac[4 * q + 0] += w4.x * vc; ac[4 * q + 1] += w4.y * vc;
            ac[4 * q + 2] += w4.z * vc; ac[4 * q + 3] += w4.w * vc;
            ap[4 * q + 0] += w4.x * vp; ap[4 * q + 1] += w4.y * vp;
            ap[4 * q + 2] += w4.z * vp; ap[4 * q + 3] += w4.w * vp;
        }
    }
#pragma unroll
    for (int o = 0; o < 16; o++) {
        ac[o] = ac[o] >= 0.f ? ac[o] : 0.2f * ac[o];
        ap[o] = ap[o] >= 0.f ? ap[o] : 0.2f * ap[o];
    }

    float ah[32];
#pragma unroll
    for (int o = 0; o < 32; o++) ah[o] = s_b0[o];
    int tb = b * 16 * TIL + ht * Wt + wt;
#pragma unroll
    for (int c = 0; c < 64; c++) {
        float v;
        if (c < 16)       v = cur[tb + c * TIL];
        else if (c < 32)  v = ac[c - 16];
        else if (c < 48)  v = g_upprev[tb + (c - 32) * TIL];
        else              v = ap[c - 48];
        const float4* wp = (const float4*)&s_w0[c * 32];
#pragma unroll
        for (int q = 0; q < 8; q++) {
            float4 w4 = wp[q];
            ah[4 * q + 0] += w4.x * v; ah[4 * q + 1] += w4.y * v;
            ah[4 * q + 2] += w4.z * v; ah[4 * q + 3] += w4.w * v;
        }
    }
    int ob = b * 32 * TIL + ht * Wt + wt;
#pragma unroll
    for (int o = 0; o < 32; o++) {
        float v = ah[o];
        v = v >= 0.f ? v : 0.2f * v;
        g_hA[ob + o * TIL] = v;
    }
}

// ---------------- kernel 4: 3x3 conv, split-OC, 4-row blocked, f32x2 ---------
// Block (32,4)=128 threads computes a 32x16 pixel tile for OCB output
// channels (o_base = half*(OCT-OCB)). Each thread: 4 rows x OCB channels.
// Per weight LDS.128 (2 ch-pairs): 8 independent FFMA2.
template <int OCT, int OCB, bool RES, bool LEAKY>
__global__ __launch_bounds__(128) void k_conv3(const float* __restrict__ in,
                                               const float* __restrict__ res,
                                               const float* __restrict__ w,
                                               const float* __restrict__ bias,
                                               float* __restrict__ out) {
    constexpr int NP = OCB / 2;   // channel pairs
    constexpr int NQ = OCB / 4;   // ulonglong2 chunks
    constexpr int IN_ROWS = 18, IN_COLS = 34;
    extern __shared__ float sm[];
    float* s_in = sm;                               // [32][18][34]
    float* s_w  = sm + 32 * IN_ROWS * IN_COLS;      // [ci][tap][OCB]

    int tx = threadIdx.x, ty = threadIdx.y;
    int tid = ty * 32 + tx;
    int x0 = blockIdx.x * 32, y0 = blockIdx.y * 16;
    int b = blockIdx.z >> 1;
    int half = blockIdx.z & 1;
    int o_base = half * (OCT - OCB);

    // stage weights [ci][tap][o_local]
    for (int t = tid; t < 32 * 9 * OCB; t += 128) {
        int lo = t % OCB;
        int ct = t / OCB;
        int ci = ct / 9, tap = ct % 9;
        s_w[t] = w[((o_base + lo) * 32 + ci) * 9 + tap];
    }
    // stage input tile with halo
    for (int t = tid; t < 32 * IN_ROWS * IN_COLS; t += 128) {
        int ci = t / (IN_ROWS * IN_COLS);
        int rm = t % (IN_ROWS * IN_COLS);
        int r = rm / IN_COLS, c2 = rm % IN_COLS;
        int gy = y0 + r - 1, gx = x0 + c2 - 1;
        float v = 0.f;
        if (gy >= 0 && gy < Ht && gx >= 0 && gx < Wt)
            v = in[((b * 32 + ci) * Ht + gy) * Wt + gx];
        s_in[t] = v;
    }
    __syncthreads();

    uint64_t acc[4][NP];
#pragma unroll
    for (int q = 0; q < NP; q++) {
        uint64_t bp = pack2(__ldg(bias + o_base + 2 * q), __ldg(bias + o_base + 2 * q + 1));
#pragma unroll
        for (int r = 0; r < 4; r++) acc[r][q] = bp;
    }

    int yloc = ty * 4;     // output rows yloc..yloc+3 (padded input rows yloc..yloc+5)
#pragma unroll 1
    for (int ci = 0; ci < 32; ci++) {
        const float* si = s_in + ci * (IN_ROWS * IN_COLS) + yloc * IN_COLS + tx;
        uint64_t iv[6][3];
#pragma unroll
        for (int rr = 0; rr < 6; rr++)
#pragma unroll
            for (int cc = 0; cc < 3; cc++)
                iv[rr][cc] = bcast2(si[rr * IN_COLS + cc]);

#pragma unroll
        for (int t = 0; t < 9; t++) {
            int dr = t / 3, dc = t % 3;
            const ulonglong2* wp = (const ulonglong2*)(s_w + (ci * 9 + t) * OCB);
#pragma unroll
            for (int q = 0; q < NQ; q++) {
                ulonglong2 w2 = wp[q];
#pragma unroll
                for (int r = 0; r < 4; r++) {
                    ffma2(acc[r][2 * q],     iv[r + dr][dc], w2.x);
                    ffma2(acc[r][2 * q + 1], iv[r + dr][dc], w2.y);
                }
            }
        }
    }

    int x = x0 + tx;
#pragma unroll
    for (int r = 0; r < 4; r++) {
        int y = y0 + yloc + r;
#pragma unroll
        for (int q = 0; q < NP; q++) {
            float v0, v1;
            unpack2(acc[r][q], v0, v1);
            int o0 = o_base + 2 * q, o1 = o0 + 1;
            if (RES) v0 += res[((b * 32 + o0) * Ht + y) * Wt + x];
            if (LEAKY) v0 = v0 >= 0.f ? v0 : 0.2f * v0;
            out[((b * OCT + o0) * Ht + y) * Wt + x] = v0;
            if (RES) v1 += res[((b * 32 + o1) * Ht + y) * Wt + x];
            if (LEAKY) v1 = v1 >= 0.f ? v1 : 0.2f * v1;
            out[((b * OCT + o1) * Ht + y) * Wt + x] = v1;
        }
    }
}

// ---------------- kernel 5: mask/select epilogue + output packing ----------------
__global__ void k_final(const float* __restrict__ cur, float* __restrict__ out) {
    int idx = blockIdx.x * blockDim.x + threadIdx.x;
    if (idx >= NT) return;
    int wt = idx % Wt;
    int ht = (idx / Wt) % Ht;
    int b = idx / TIL;
    int p = ht * Wt + wt;
    const float* u = g_u + b * 34 * TIL + p;
    float c0 = u[0];
    float c1 = u[TIL];
    bool pick_cur = (c1 > c0);

    float* o1 = out + b * 16 * TIL + p;
    float* o2 = out + B * 16 * TIL + b * 17 * TIL + p;
    float* o3 = out + B * 16 * TIL + B * 17 * TIL + b * 17 * TIL + p;
#pragma unroll
    for (int c = 0; c < 16; c++) {
        float uc = cur[b * 16 * TIL + c * TIL + p] + u[(18 + c) * TIL];
        float up = g_upprev[b * 16 * TIL + c * TIL + p] + u[(2 + c) * TIL];
        if (c == 0) { uc = fmaxf(uc, 0.f); up = fmaxf(up, 0.f); }
        o1[c * TIL] = pick_cur ? uc : up;
        o2[c * TIL] = uc;
        o3[c * TIL] = up;
    }
    o2[16 * TIL] = c1;
    o3[16 * TIL] = c0;
}

// ---------------- launch ----------------
extern "C" void kernel_launch(void* const* d_in, const int* in_sizes, int n_in,
                              void* d_out, int out_size) {
    const float* fea_l  = (const float*)d_in[0];
    const float* fea_r  = (const float*)d_in[1];
    const float* cur    = (const float*)d_in[2];
    const float* prev   = (const float*)d_in[3];
    const float* w_dec  = (const float*)d_in[4];
    const float* b_dec  = (const float*)d_in[5];
    const float* w0     = (const float*)d_in[6];
    const float* b0     = (const float*)d_in[7];
    const float* w_r0c1 = (const float*)d_in[8];
    const float* b_r0c1 = (const float*)d_in[9];
    const float* w_r0c2 = (const float*)d_in[10];
    const float* b_r0c2 = (const float*)d_in[11];
    const float* w_r1c1 = (const float*)d_in[12];
    const float* b_r1c1 = (const float*)d_in[13];
    const float* w_r1c2 = (const float*)d_in[14];
    const float* b_r1c2 = (const float*)d_in[15];
    const float* w_last = (const float*)d_in[16];
    const float* b_last = (const float*)d_in[17];
    float* out = (float*)d_out;

    void *pA, *pB, *pC, *pU;
    cudaGetSymbolAddress(&pA, g_hA);
    cudaGetSymbolAddress(&pB, g_hB);
    cudaGetSymbolAddress(&pC, g_hC);
    cudaGetSymbolAddress(&pU, g_u);
    float* hA = (float*)pA;
    float* hB = (float*)pB;
    float* hC = (float*)pC;
    float* uB = (float*)pU;

    constexpr int SMIN = 32 * 18 * 34 * 4;                   // 78336 B input tile
    constexpr int SM16 = SMIN + 32 * 9 * 16 * 4;             // + 18432 = 96768 B
    constexpr int SM20 = SMIN + 32 * 9 * 20 * 4;             // + 23040 = 101376 B
    cudaFuncSetAttribute(k_conv3<32, 16, false, true>,
                         cudaFuncAttributeMaxDynamicSharedMemorySize, SM16);
    cudaFuncSetAttribute(k_conv3<32, 16, true, true>,
                         cudaFuncAttributeMaxDynamicSharedMemorySize, SM16);
    cudaFuncSetAttribute(k_conv3<34, 20, false, false>,
                         cudaFuncAttributeMaxDynamicSharedMemorySize, SM20);

    k_upsample<<<(B * 16 * TIL + 255) / 256, 256>>>(prev);
    k_warpcv<<<(FULL + 127) / 128, 128>>>(fea_l, fea_r, cur);
    k_fused1x1<<<(NT + 127) / 128, 128>>>(cur, w_dec, b_dec, w0, b0);

    dim3 cb(32, 4);
    dim3 cg(Wt / 32, Ht / 16, B * 2);   // (10, 6, 4) = 240 blocks
    k_conv3<32, 16, false, true><<<cg, cb, SM16>>>(hA, nullptr, w_r0c1, b_r0c1, hB);
    k_conv3<32, 16, true,  true><<<cg, cb, SM16>>>(hB, hA, w_r0c2, b_r0c2, hC);
    k_conv3<32, 16, false, true><<<cg, cb, SM16>>>(hC, nullptr, w_r1c1, b_r1c1, hB);
    k_conv3<32, 16, true,  true><<<cg, cb, SM16>>>(hB, hC, w_r1c2, b_r1c2, hA);
    k_conv3<34, 20, false, false><<<cg, cb, SM20>>>(hA, nullptr, w_last, b_last, uB);
    k_final<<<(NT + 255) / 256, 256>>>(cur, out);
}

// round 4
// speedup vs baseline: 1.2311x; 1.0669x over previous
#include <cuda_runtime.h>
#include <cstdint>

// ---------------- problem constants ----------------
constexpr int B  = 2;
constexpr int C  = 16;
constexpr int H  = 384;
constexpr int W  = 1280;
constexpr int Ht = 96;
constexpr int Wt = 320;
constexpr int HW   = H * W;        // 491520
constexpr int FULL = B * H * W;    // 983040
constexpr int TIL  = Ht * Wt;      // 30720
constexpr int NT   = B * TIL;      // 61440
constexpr int Hp = 48, Wp = 160;   // prev hypothesis resolution

// ---------------- scratch (device globals; no allocation) ----------------
__device__ float g_upprev[B * 16 * TIL];
__device__ float g_sumabs[FULL];
__device__ float g_cv[6][FULL];
__device__ float g_hA[B * 32 * TIL];
__device__ float g_hB[B * 32 * TIL];
__device__ float g_hC[B * 32 * TIL];
__device__ float g_u[B * 34 * TIL];

// ---------------- f32x2 packed helpers ----------------
__device__ __forceinline__ void ffma2(uint64_t& d, uint64_t a, uint64_t b) {
    asm("fma.rn.f32x2 %0, %1, %2, %0;" : "+l"(d) : "l"(a), "l"(b));
}
__device__ __forceinline__ uint64_t pack2(float lo, float hi) {
    uint64_t r;
    asm("mov.b64 %0, {%1, %2};" : "=l"(r) : "f"(lo), "f"(hi));
    return r;
}
__device__ __forceinline__ uint64_t bcast2(float v) {
    uint64_t r;
    asm("mov.b64 %0, {%1, %1};" : "=l"(r) : "f"(v));
    return r;
}
__device__ __forceinline__ void unpack2(uint64_t a, float& lo, float& hi) {
    asm("mov.b64 {%0, %1}, %2;" : "=f"(lo), "=f"(hi) : "l"(a));
}

// ---------------- kernel 1: upsample_hyp(prev, scale=2, size=2) ----------------
__global__ void k_upsample(const float* __restrict__ prev) {
    int idx = blockIdx.x * blockDim.x + threadIdx.x;
    if (idx >= B * 16 * TIL) return;
    int x = idx % Wt;
    int y = (idx / Wt) % Ht;
    int c = (idx / TIL) % 16;
    int b = idx / (16 * TIL);
    int xh = x >> 1, yh = y >> 1;
    const float* p = prev + (size_t)b * 16 * Hp * Wp;
    int off = yh * Wp + xh;
    float v;
    if (c == 0) {
        float cx = (x & 1) ? 0.5f : -0.5f;
        float cy = (y & 1) ? 0.5f : -0.5f;
        v = 2.0f * (p[off] + cx * p[Hp * Wp + off] + cy * p[2 * Hp * Wp + off]);
    } else {
        v = p[c * Hp * Wp + off];
    }
    g_upprev[idx] = v;
}

// ---------------- kernel 2: fused fea + 6 cost volumes ----------------
__global__ __launch_bounds__(128) void k_warpcv(const float* __restrict__ fea_l,
                                                const float* __restrict__ fea_r,
                                                const float* __restrict__ cur) {
    int idx = blockIdx.x * blockDim.x + threadIdx.x;
    if (idx >= FULL) return;
    int x = idx % W;
    int y = (idx / W) % H;
    int b = idx / (H * W);
    int ht = y >> 2, wt = x >> 2;
    float cx = (float)(x & 3) - 1.5f;
    float cy = (float)(y & 3) - 1.5f;

    int toff = b * 16 * TIL + ht * Wt + wt;
    float bc = cur[toff] + cx * cur[toff + TIL] + cy * cur[toff + 2 * TIL];
    float bp = g_upprev[toff] + cx * g_upprev[toff + TIL] + cy * g_upprev[toff + 2 * TIL];

    float w0a[6], w1a[6];
    int   xa[6], xb[6];
#pragma unroll
    for (int j = 0; j < 6; j++) {
        float ld = ((j < 3) ? bc : bp) + (float)(j % 3 - 1);
        float ix = (float)x - ld;
        float x0f = floorf(ix);
        float wx = ix - x0f;
        int x0 = (int)x0f;
        int x1 = x0 + 1;
        float o0 = (x0 >= 0 && x0 < W) ? 1.f : 0.f;
        float o1 = (x1 >= 0 && x1 < W) ? 1.f : 0.f;
        w0a[j] = (1.f - wx) * o0;
        w1a[j] = wx * o1;
        xa[j] = min(max(x0, 0), W - 1);
        xb[j] = min(max(x1, 0), W - 1);
    }

    float acc[6] = {0.f, 0.f, 0.f, 0.f, 0.f, 0.f};
    float sa = 0.f;
    const float* fl = fea_l + (size_t)b * C * HW + y * W + x;
    const float* fr = fea_r + (size_t)b * C * HW + y * W;
#pragma unroll 4
    for (int c = 0; c < C; c++) {
        float l = fl[c * HW];
        sa += fabsf(l);
        const float* r = fr + c * HW;
#pragma unroll
        for (int j = 0; j < 6; j++) {
            float v = w0a[j] * __ldg(r + xa[j]) + w1a[j] * __ldg(r + xb[j]);
            acc[j] += fabsf(l - v);
        }
    }
    g_sumabs[idx] = sa;
#pragma unroll
    for (int j = 0; j < 6; j++) g_cv[j][idx] = acc[j];
}

// ---------------- kernel 3: fused 1x1 convs (dec x2 + w0) ----------------
__global__ __launch_bounds__(128) void k_fused1x1(const float* __restrict__ cur,
                                                  const float* __restrict__ w_dec,
                                                  const float* __restrict__ b_dec,
                                                  const float* __restrict__ w0,
                                                  const float* __restrict__ b0) {
    __shared__ float s_wd[64 * 16];
    __shared__ float s_w0[64 * 32];
    __shared__ float s_bd[16], s_b0[32];
    for (int t = threadIdx.x; t < 64 * 16; t += blockDim.x) {
        int c = t >> 4, o = t & 15;
        s_wd[t] = w_dec[o * 64 + c];
    }
    for (int t = threadIdx.x; t < 64 * 32; t += blockDim.x) {
        int c = t >> 5, o = t & 31;
        s_w0[t] = w0[o * 64 + c];
    }
    if (threadIdx.x < 16) s_bd[threadIdx.x] = b_dec[threadIdx.x];
    if (threadIdx.x < 32) s_b0[threadIdx.x] = b0[threadIdx.x];
    __syncthreads();

    int idx = blockIdx.x * blockDim.x + threadIdx.x;
    if (idx >= NT) return;
    int wt = idx % Wt;
    int ht = (idx / Wt) % Ht;
    int b = idx / TIL;

    float ac[16], ap[16];
#pragma unroll
    for (int o = 0; o < 16; o++) { ac[o] = s_bd[o]; ap[o] = s_bd[o]; }

#pragma unroll
    for (int c = 0; c < 64; c++) {
        int ry = (c >> 2) & 3, rx = c & 3;
        int fidx = (b * H + 4 * ht + ry) * W + 4 * wt + rx;
        float vc, vp;
        if (c < 16) {
            float s = g_sumabs[fidx];
            vc = s; vp = s;
        } else {
            int k = (c - 16) >> 4;
            vc = g_cv[k][fidx];
            vp = g_cv[3 + k][fidx];
        }
        const float4* wp = (const float4*)&s_wd[c * 16];
#pragma unroll
        for (int q = 0; q < 4; q++) {
            float4 w4 = wp[q];
            ac[4 * q + 0] += w4.x * vc; ac[4 * q + 1] += w4.y * vc;
            ac[4 * q + 2] += w4.z * vc; ac[4 * q + 3] += w4.w * vc;
            ap[4 * q + 0] += w4.x * vp; ap[4 * q + 1] += w4.y * vp;
            ap[4 * q + 2] += w4.z * vp; ap[4 * q + 3] += w4.w * vp;
        }
    }
#pragma unroll
    for (int o = 0; o < 16; o++) {
        ac[o] = ac[o] >= 0.f ? ac[o] : 0.2f * ac[o];
        ap[o] = ap[o] >= 0.f ? ap[o] : 0.2f * ap[o];
    }

    float ah[32];
#pragma unroll
    for (int o = 0; o < 32; o++) ah[o] = s_b0[o];
    int tb = b * 16 * TIL + ht * Wt + wt;
#pragma unroll
    for (int c = 0; c < 64; c++) {
        float v;
        if (c < 16)       v = cur[tb + c * TIL];
        else if (c < 32)  v = ac[c - 16];
        else if (c < 48)  v = g_upprev[tb + (c - 32) * TIL];
        else              v = ap[c - 48];
        const float4* wp = (const float4*)&s_w0[c * 32];
#pragma unroll
        for (int q = 0; q < 8; q++) {
            float4 w4 = wp[q];
            ah[4 * q + 0] += w4.x * v; ah[4 * q + 1] += w4.y * v;
            ah[4 * q + 2] += w4.z * v; ah[4 * q + 3] += w4.w * v;
        }
    }
    int ob = b * 32 * TIL + ht * Wt + wt;
#pragma unroll
    for (int o = 0; o < 32; o++) {
        float v = ah[o];
        v = v >= 0.f ? v : 0.2f * v;
        g_hA[ob + o * TIL] = v;
    }
}

// ---------------- kernel 4: 3x3 conv, direct-LDG input, weights in smem ------
// Block (32,4)=128 threads computes a 32x8 tile for OCB output channels.
// Each thread: 2 rows x OCB channels. Input read straight from L1/L2 (no
// input smem, no staging barrier); only weights staged in smem.
template <int OCT, int OCB, bool RES, bool LEAKY>
__global__ __launch_bounds__(128) void k_conv3(const float* __restrict__ in,
                                               const float* __restrict__ res,
                                               const float* __restrict__ w,
                                               const float* __restrict__ bias,
                                               float* __restrict__ out) {
    constexpr int NP = OCB / 2;   // channel pairs
    constexpr int NQ = OCB / 4;   // ulonglong2 chunks
    __shared__ float s_w[32 * 9 * OCB];

    int tx = threadIdx.x, ty = threadIdx.y;
    int tid = ty * 32 + tx;
    int x0 = blockIdx.x * 32, y0 = blockIdx.y * 8;
    int b = blockIdx.z >> 1;
    int half = blockIdx.z & 1;
    int o_base = half * (OCT - OCB);

    // stage weights [ci][tap][o_local]
    for (int t = tid; t < 32 * 9 * OCB; t += 128) {
        int lo = t % OCB;
        int ct = t / OCB;
        int ci = ct / 9, tap = ct % 9;
        s_w[t] = w[((o_base + lo) * 32 + ci) * 9 + tap];
    }
    __syncthreads();

    uint64_t acc[2][NP];
#pragma unroll
    for (int q = 0; q < NP; q++) {
        uint64_t bp = pack2(__ldg(bias + o_base + 2 * q), __ldg(bias + o_base + 2 * q + 1));
        acc[0][q] = bp;
        acc[1][q] = bp;
    }

    int yloc = ty * 2;                 // output rows y0+yloc, y0+yloc+1
    int gybase = y0 + yloc - 1;        // input rows gybase .. gybase+3
    int gxbase = x0 + tx - 1;          // input cols gxbase .. gxbase+2

    bool py[4], px[3];
#pragma unroll
    for (int r = 0; r < 4; r++) py[r] = (unsigned)(gybase + r) < (unsigned)Ht;
#pragma unroll
    for (int c = 0; c < 3; c++) px[c] = (unsigned)(gxbase + c) < (unsigned)Wt;

    const float* pin = in + ((size_t)(b * 32) * Ht + gybase) * Wt + gxbase;

#pragma unroll 1
    for (int ci = 0; ci < 32; ci++) {
        uint64_t iv[4][3];
#pragma unroll
        for (int r = 0; r < 4; r++)
#pragma unroll
            for (int c = 0; c < 3; c++) {
                float v = (py[r] && px[c]) ? __ldg(pin + r * Wt + c) : 0.f;
                iv[r][c] = bcast2(v);
            }
        pin += Ht * Wt;

#pragma unroll
        for (int t = 0; t < 9; t++) {
            int dr = t / 3, dc = t % 3;
            const ulonglong2* wp = (const ulonglong2*)(s_w + (ci * 9 + t) * OCB);
#pragma unroll
            for (int q = 0; q < NQ; q++) {
                ulonglong2 w2 = wp[q];
                ffma2(acc[0][2 * q],     iv[dr][dc],     w2.x);
                ffma2(acc[0][2 * q + 1], iv[dr][dc],     w2.y);
                ffma2(acc[1][2 * q],     iv[dr + 1][dc], w2.x);
                ffma2(acc[1][2 * q + 1], iv[dr + 1][dc], w2.y);
            }
        }
    }

    int x = x0 + tx;
#pragma unroll
    for (int r = 0; r < 2; r++) {
        int y = y0 + yloc + r;
#pragma unroll
        for (int q = 0; q < NP; q++) {
            float v0, v1;
            unpack2(acc[r][q], v0, v1);
            int o0 = o_base + 2 * q, o1 = o0 + 1;
            if (RES) v0 += res[((b * 32 + o0) * Ht + y) * Wt + x];
            if (LEAKY) v0 = v0 >= 0.f ? v0 : 0.2f * v0;
            out[((b * OCT + o0) * Ht + y) * Wt + x] = v0;
            if (RES) v1 += res[((b * 32 + o1) * Ht + y) * Wt + x];
            if (LEAKY) v1 = v1 >= 0.f ? v1 : 0.2f * v1;
            out[((b * OCT + o1) * Ht + y) * Wt + x] = v1;
        }
    }
}

// ---------------- kernel 5: mask/select epilogue + output packing ----------------
__global__ void k_final(const float* __restrict__ cur, float* __restrict__ out) {
    int idx = blockIdx.x * blockDim.x + threadIdx.x;
    if (idx >= NT) return;
    int wt = idx % Wt;
    int ht = (idx / Wt) % Ht;
    int b = idx / TIL;
    int p = ht * Wt + wt;
    const float* u = g_u + b * 34 * TIL + p;
    float c0 = u[0];
    float c1 = u[TIL];
    bool pick_cur = (c1 > c0);

    float* o1 = out + b * 16 * TIL + p;
    float* o2 = out + B * 16 * TIL + b * 17 * TIL + p;
    float* o3 = out + B * 16 * TIL + B * 17 * TIL + b * 17 * TIL + p;
#pragma unroll
    for (int c = 0; c < 16; c++) {
        float uc = cur[b * 16 * TIL + c * TIL + p] + u[(18 + c) * TIL];
        float up = g_upprev[b * 16 * TIL + c * TIL + p] + u[(2 + c) * TIL];
        if (c == 0) { uc = fmaxf(uc, 0.f); up = fmaxf(up, 0.f); }
        o1[c * TIL] = pick_cur ? uc : up;
        o2[c * TIL] = uc;
        o3[c * TIL] = up;
    }
    o2[16 * TIL] = c1;
    o3[16 * TIL] = c0;
}

// ---------------- launch ----------------
extern "C" void kernel_launch(void* const* d_in, const int* in_sizes, int n_in,
                              void* d_out, int out_size) {
    const float* fea_l  = (const float*)d_in[0];
    const float* fea_r  = (const float*)d_in[1];
    const float* cur    = (const float*)d_in[2];
    const float* prev   = (const float*)d_in[3];
    const float* w_dec  = (const float*)d_in[4];
    const float* b_dec  = (const float*)d_in[5];
    const float* w0     = (const float*)d_in[6];
    const float* b0     = (const float*)d_in[7];
    const float* w_r0c1 = (const float*)d_in[8];
    const float* b_r0c1 = (const float*)d_in[9];
    const float* w_r0c2 = (const float*)d_in[10];
    const float* b_r0c2 = (const float*)d_in[11];
    const float* w_r1c1 = (const float*)d_in[12];
    const float* b_r1c1 = (const float*)d_in[13];
    const float* w_r1c2 = (const float*)d_in[14];
    const float* b_r1c2 = (const float*)d_in[15];
    const float* w_last = (const float*)d_in[16];
    const float* b_last = (const float*)d_in[17];
    float* out = (float*)d_out;

    void *pA, *pB, *pC, *pU;
    cudaGetSymbolAddress(&pA, g_hA);
    cudaGetSymbolAddress(&pB, g_hB);
    cudaGetSymbolAddress(&pC, g_hC);
    cudaGetSymbolAddress(&pU, g_u);
    float* hA = (float*)pA;
    float* hB = (float*)pB;
    float* hC = (float*)pC;
    float* uB = (float*)pU;

    k_upsample<<<(B * 16 * TIL + 255) / 256, 256>>>(prev);
    k_warpcv<<<(FULL + 127) / 128, 128>>>(fea_l, fea_r, cur);
    k_fused1x1<<<(NT + 127) / 128, 128>>>(cur, w_dec, b_dec, w0, b0);

    dim3 cb(32, 4);
    dim3 cg(Wt / 32, Ht / 8, B * 2);   // (10, 12, 4) = 480 blocks
    k_conv3<32, 16, false, true><<<cg, cb>>>(hA, nullptr, w_r0c1, b_r0c1, hB);
    k_conv3<32, 16, true,  true><<<cg, cb>>>(hB, hA, w_r0c2, b_r0c2, hC);
    k_conv3<32, 16, false, true><<<cg, cb>>>(hC, nullptr, w_r1c1, b_r1c1, hB);
    k_conv3<32, 16, true,  true><<<cg, cb>>>(hB, hC, w_r1c2, b_r1c2, hA);
    k_conv3<34, 20, false, false><<<cg, cb>>>(hA, nullptr, w_last, b_last, uB);
    k_final<<<(NT + 255) / 256, 256>>>(cur, out);
}